// round 2
// baseline (speedup 1.0000x reference)
#include <cuda_runtime.h>
#include <cuda_bf16.h>
#include <math.h>

#define CELLN 14
#define NCLS  80
#define BPC   3
#define FEAT  95            // 80 + 3 + 12
#define CELLS2 196          // 14*14
#define PRED_PER_B 18620    // 196*95
#define CSF   32.0f
#define IMGF  448.0f
#define EPSF  1e-9f
#define INV_PI2_4 0.40528473456935109f   // 4/pi^2
#define MAXB  4096

__device__ float2 g_stats[MAXB * CELLS2];   // per-(batch,cell): {class sumsq, conf sumsq}
__device__ float  g_batch_loss[MAXB];
__device__ int    g_count = 0;

// ---------------------------------------------------------------------------
// Kernel A: warp per (batch,cell) row. Coalesced read of the 95 floats,
// warp-reduce class sum-of-squares and confidence sum-of-squares.
// ---------------------------------------------------------------------------
__global__ __launch_bounds__(256)
void yolo_stats_kernel(const float* __restrict__ P, int ncells)
{
    const int warp = (blockIdx.x * 256 + threadIdx.x) >> 5;
    const int lane = threadIdx.x & 31;
    if (warp >= ncells) return;

    const float* p = P + (size_t)warp * FEAT;
    const float a = p[lane];
    const float bb = p[lane + 32];
    const float c = (lane < 31) ? p[lane + 64] : 0.0f;

    float cls  = a * a + bb * bb;          // indices [0,31] and [32,63]: all class
    float conf = 0.0f;
    const float c2 = c * c;                // index lane+64 in [64,94]
    if (lane < 16)      cls  += c2;        // 64..79: class
    else if (lane < 19) conf  = c2;        // 80..82: confidence

    #pragma unroll
    for (int off = 16; off; off >>= 1) {
        cls  += __shfl_xor_sync(0xFFFFFFFFu, cls,  off);
        conf += __shfl_xor_sync(0xFFFFFFFFu, conf, off);
    }
    if (lane == 0) g_stats[warp] = make_float2(cls, conf);
}

// ---------------------------------------------------------------------------
// Kernel B: one CTA per batch. Per-object work using precomputed stats;
// scattered reads of predicts hit L2 (76MB < 126MB, just streamed by A).
// Final batch-sum fused via last-block-done pattern.
// ---------------------------------------------------------------------------
__global__ __launch_bounds__(256)
void yolo_obj_kernel(const float* __restrict__ predicts,
                     const float* __restrict__ labels,
                     const int*   __restrict__ objects_num,
                     float* __restrict__ out, int B, int M)
{
    __shared__ float2 sstats[CELLS2];
    __shared__ float  slab[320];
    __shared__ float  sred[8];
    __shared__ float  sS;
    __shared__ int    s_last;

    const int b    = blockIdx.x;
    const int tid  = threadIdx.x;
    const int lane = tid & 31;
    const int wid  = tid >> 5;

    // stage stats + labels
    if (tid < CELLS2) sstats[tid] = g_stats[b * CELLS2 + tid];
    for (int i = tid; i < M * 5; i += 256) slab[i] = labels[(size_t)b * M * 5 + i];
    __syncthreads();

    // total confidence sum-of-squares for this batch
    float cs = 0.0f;
    for (int c = tid; c < CELLS2; c += 256) cs += sstats[c].y;
    #pragma unroll
    for (int off = 16; off; off >>= 1) cs += __shfl_xor_sync(0xFFFFFFFFu, cs, off);
    if (lane == 0) sred[wid] = cs;
    __syncthreads();
    if (tid == 0) {
        float s = 0.0f;
        #pragma unroll
        for (int i = 0; i < 8; i++) s += sred[i];
        sS = s;
    }
    __syncthreads();
    const float S_conf2 = sS;
    __syncthreads();            // sred reused below

    int nobj = objects_num[b];
    if (nobj > M) nobj = M;

    const float* pb = predicts + (size_t)b * PRED_PER_B;

    float wacc = 0.0f;
    for (int o = wid; o < nobj; o += 8) {
        const float* l = slab + o * 5;
        const float x = l[0], y = l[1], w = l[2], h = l[3];
        const int   k = (int)l[4];

        const int ix0 = (int)floorf((x - 0.5f * w) * (1.0f / CSF));
        const int ix1 = (int)fminf(ceilf((x + 0.5f * w) * (1.0f / CSF)), (float)CELLN);
        const int iy0 = (int)floorf((y - 0.5f * h) * (1.0f / CSF));
        const int iy1 = (int)fminf(ceilf((y + 0.5f * h) * (1.0f / CSF)), (float)CELLN);
        const int nx  = max(0, ix1 - ix0);
        const int ny  = max(0, iy1 - iy0);
        const int cnt = nx * ny;

        // class loss over masked cells: sumP2 - 2 p_k + 1
        float cls = 0.0f;
        for (int t = lane; t < cnt; t += 32) {
            const int iy = iy0 + t / nx;
            const int ix = ix0 + t % nx;
            const int cell = iy * CELLN + ix;
            cls += sstats[cell].x - 2.0f * pb[cell * FEAT + k] + 1.0f;
        }
        #pragma unroll
        for (int off = 16; off; off >>= 1)
            cls += __shfl_xor_sync(0xFFFFFFFFu, cls, off);

        // center cell
        const int cx = (int)floorf(x * (1.0f / CSF));
        const int cy = (int)floorf(y * (1.0f / CSF));
        const float* pc = pb + (cy * CELLN + cx) * FEAT;

        float ciou = -1e30f;
        float pC = 0.f, px = 0.f, py = 0.f, pw = 0.f, ph = 0.f;
        if (lane < BPC) {
            pC = pc[NCLS + lane];
            const float* bx = pc + NCLS + BPC + 4 * lane;
            px = bx[0] * CSF + (float)cx * CSF;
            py = bx[1] * CSF + (float)cy * CSF;
            pw = bx[2] * IMGF;
            ph = bx[3] * IMGF;

            // CIoU exactly per reference (incl. its centers-vs-widths enclose quirk)
            const float x11 = px - 0.5f * pw, x12 = px + 0.5f * pw;
            const float y11 = py - 0.5f * ph, y12 = py + 0.5f * ph;
            const float x21 = x - 0.5f * w,   x22 = x + 0.5f * w;
            const float y21 = y - 0.5f * h,   y22 = y + 0.5f * h;
            const float iw = fmaxf(fminf(x12, x22) - fmaxf(x11, x21), 0.0f);
            const float ih = fmaxf(fminf(y12, y22) - fmaxf(y11, y21), 0.0f);
            const float inter = iw * ih;
            const float uni = pw * ph + w * h - inter;
            const float iou = inter / (uni + EPSF);
            const float cd  = (px - x) * (px - x) + (py - y) * (py - y);
            const float el = fminf(px, x), er = fmaxf(pw, w);
            const float et = fminf(py, y), eb = fmaxf(ph, h);
            const float ed = (er - el) * (er - el) + (eb - et) * (eb - et);
            const float da = atanf(w / (h + EPSF)) - atanf(pw / (ph + EPSF));
            const float v  = INV_PI2_4 * da * da;
            const float alpha = v / (1.0f - iou + v + EPSF);
            ciou = iou - cd / (ed + EPSF) - alpha * v;
        }
        float m = ciou;
        m = fmaxf(m, __shfl_xor_sync(0xFFFFFFFFu, m, 1));
        m = fmaxf(m, __shfl_xor_sync(0xFFFFFFFFu, m, 2));

        float contrib = 0.0f;
        if (lane < BPC && ciou >= m) {
            const float d = pC - ciou;
            contrib += 0.5f * d * d;           // object loss
            contrib -= 0.25f * pC * pC;        // removed from noobject term
            const float dx = (px - x) * (1.0f / CSF);
            const float dy = (py - y) * (1.0f / CSF);
            const float swp = sqrtf(fminf(fmaxf(pw, 0.0f), IMGF));
            const float shp = sqrtf(fminf(fmaxf(ph, 0.0f), IMGF));
            const float dw = swp - sqrtf(fabsf(w));
            const float dh = shp - sqrtf(fabsf(h));
            contrib += 5.0f * (0.5f * dx * dx + 0.5f * dy * dy
                               + (0.5f * dw * dw) * (1.0f / IMGF)
                               + (0.5f * dh * dh) * (1.0f / IMGF));
        }
        contrib += __shfl_xor_sync(0xFFFFFFFFu, contrib, 1);
        contrib += __shfl_xor_sync(0xFFFFFFFFu, contrib, 2);

        if (lane == 0)
            wacc += 0.5f * cls + contrib + 0.25f * S_conf2;
    }

    if (lane == 0) sred[wid] = wacc;
    __syncthreads();
    if (tid == 0) {
        float s = 0.0f;
        #pragma unroll
        for (int i = 0; i < 8; i++) s += sred[i];
        g_batch_loss[b] = s;
        __threadfence();
        int prev = atomicAdd(&g_count, 1);
        s_last = (prev == B - 1);
    }
    __syncthreads();

    // last finished block performs the deterministic final reduction
    if (s_last) {
        float a = 0.0f;
        for (int i = tid; i < B; i += 256) a += g_batch_loss[i];
        #pragma unroll
        for (int off = 16; off; off >>= 1) a += __shfl_xor_sync(0xFFFFFFFFu, a, off);
        if (lane == 0) sred[wid] = a;
        __syncthreads();
        if (tid == 0) {
            float s = 0.0f;
            #pragma unroll
            for (int i = 0; i < 8; i++) s += sred[i];
            out[0] = s / (float)B;
            g_count = 0;          // reset for next graph replay
        }
    }
}

extern "C" void kernel_launch(void* const* d_in, const int* in_sizes, int n_in,
                              void* d_out, int out_size)
{
    const float* predicts = (const float*)d_in[0];
    const float* labels   = (const float*)d_in[1];
    const int*   objnum   = (const int*)d_in[2];
    float* out = (float*)d_out;

    const int B = in_sizes[2];
    const int M = in_sizes[1] / (B * 5);
    const int ncells = B * CELLS2;

    const int gridA = (ncells * 32 + 255) / 256;
    yolo_stats_kernel<<<gridA, 256>>>(predicts, ncells);
    yolo_obj_kernel<<<B, 256>>>(predicts, labels, objnum, out, B, M);
}

// round 3
// speedup vs baseline: 1.2193x; 1.2193x over previous
#include <cuda_runtime.h>
#include <cuda_bf16.h>
#include <math.h>

#define CELLN 14
#define NCLS  80
#define BPC   3
#define FEAT  95            // 80 + 3 + 12
#define CELLS2 196          // 14*14
#define PRED_PER_B 18620    // 196*95
#define CSF   32.0f
#define IMGF  448.0f
#define EPSF  1e-9f
#define INV_PI2_4 0.40528473456935109f   // 4/pi^2
#define MAXB  4096

__device__ float g_batch_loss[MAXB];
__device__ int   g_count = 0;

// ---------------------------------------------------------------------------
// Single fused kernel: one CTA (8 warps) per batch element.
//  Phase 1: warp-per-cell coalesced stream of the 95 floats; inline per-cell
//           class sum-of-squares (-> smem) and conf sum-of-squares (-> reg);
//           tail 15 floats (conf + boxes) kept in smem.
//  Phase 2: per-object losses from smem (+ L1/L2-resident p_k gather).
//  Phase 3: last-finished CTA does the deterministic batch reduction.
// ---------------------------------------------------------------------------
__global__ __launch_bounds__(256)
void yolo_fused_kernel(const float* __restrict__ predicts,
                       const float* __restrict__ labels,
                       const int*   __restrict__ objects_num,
                       float* __restrict__ out, int B, int M)
{
    __shared__ float scell[CELLS2 * 16];   // per cell: features 80..94 (15 used)
    __shared__ float ssum2[CELLS2];        // per cell: class sum of squares
    __shared__ float sred[8];
    __shared__ float sS;
    __shared__ int   s_last;

    const int b    = blockIdx.x;
    const int tid  = threadIdx.x;
    const int lane = tid & 31;
    const int wid  = tid >> 5;

    const float* pb = predicts + (size_t)b * PRED_PER_B;

    // ---- Phase 1: stream + inline stats ----
    float conf2 = 0.0f;                    // per-thread conf sumsq accumulator
    for (int cell = wid; cell < CELLS2; cell += 8) {
        const float* p = pb + cell * FEAT;
        const float a = p[lane];
        const float bv = p[lane + 32];
        const float c = (lane < 31) ? p[lane + 64] : 0.0f;

        float cls = a * a + bv * bv;       // features [0,64)
        if (lane < 16) cls += c * c;       // features 64..79
        else if (lane < 19) conf2 += c * c;   // features 80..82 (confidence)
        if (lane >= 16 && lane < 31)
            scell[cell * 16 + (lane - 16)] = c;   // features 80..94

        #pragma unroll
        for (int off = 16; off; off >>= 1)
            cls += __shfl_xor_sync(0xFFFFFFFFu, cls, off);
        if (lane == 0) ssum2[cell] = cls;
    }
    // reduce conf sumsq across block
    #pragma unroll
    for (int off = 16; off; off >>= 1)
        conf2 += __shfl_xor_sync(0xFFFFFFFFu, conf2, off);
    if (lane == 0) sred[wid] = conf2;
    __syncthreads();
    if (tid == 0) {
        float s = 0.0f;
        #pragma unroll
        for (int i = 0; i < 8; i++) s += sred[i];
        sS = s;
    }
    __syncthreads();
    const float S_conf2 = sS;
    __syncthreads();            // sred reused below

    // ---- Phase 2: per-object work ----
    int nobj = objects_num[b];
    if (nobj > M) nobj = M;
    const float* lb = labels + (size_t)b * M * 5;

    float wacc = 0.0f;
    for (int o = wid; o < nobj; o += 8) {
        const float x = lb[o * 5 + 0], y = lb[o * 5 + 1];
        const float w = lb[o * 5 + 2], h = lb[o * 5 + 3];
        const int   k = (int)lb[o * 5 + 4];

        const int ix0 = (int)floorf((x - 0.5f * w) * (1.0f / CSF));
        const int ix1 = (int)fminf(ceilf((x + 0.5f * w) * (1.0f / CSF)), (float)CELLN);
        const int iy0 = (int)floorf((y - 0.5f * h) * (1.0f / CSF));
        const int iy1 = (int)fminf(ceilf((y + 0.5f * h) * (1.0f / CSF)), (float)CELLN);
        const int nx  = max(0, ix1 - ix0);
        const int ny  = max(0, iy1 - iy0);
        const int cnt = nx * ny;

        // class loss over masked cells: ssum2[cell] - 2 p_k + 1
        // p_k gathered from global (just streamed by this CTA -> L1/L2 hit)
        float cls = 0.0f;
        for (int t = lane; t < cnt; t += 32) {
            const int iy = iy0 + t / nx;
            const int ix = ix0 + t % nx;
            const int cell = iy * CELLN + ix;
            cls += ssum2[cell] - 2.0f * __ldg(pb + cell * FEAT + k) + 1.0f;
        }
        #pragma unroll
        for (int off = 16; off; off >>= 1)
            cls += __shfl_xor_sync(0xFFFFFFFFu, cls, off);

        // center cell (conf + boxes live in smem)
        const int cx = (int)floorf(x * (1.0f / CSF));
        const int cy = (int)floorf(y * (1.0f / CSF));
        const float* sc = scell + (cy * CELLN + cx) * 16;

        float ciou = -1e30f;
        float pC = 0.f, px = 0.f, py = 0.f, pw = 0.f, ph = 0.f;
        if (lane < BPC) {
            pC = sc[lane];                       // features 80..82
            const float* bx = sc + BPC + 4 * lane;  // features 83..94
            px = bx[0] * CSF + (float)cx * CSF;
            py = bx[1] * CSF + (float)cy * CSF;
            pw = bx[2] * IMGF;
            ph = bx[3] * IMGF;

            // CIoU exactly per reference (incl. centers-vs-widths enclose quirk)
            const float x11 = px - 0.5f * pw, x12 = px + 0.5f * pw;
            const float y11 = py - 0.5f * ph, y12 = py + 0.5f * ph;
            const float x21 = x - 0.5f * w,   x22 = x + 0.5f * w;
            const float y21 = y - 0.5f * h,   y22 = y + 0.5f * h;
            const float iw = fmaxf(fminf(x12, x22) - fmaxf(x11, x21), 0.0f);
            const float ih = fmaxf(fminf(y12, y22) - fmaxf(y11, y21), 0.0f);
            const float inter = iw * ih;
            const float uni = pw * ph + w * h - inter;
            const float iou = inter / (uni + EPSF);
            const float cd  = (px - x) * (px - x) + (py - y) * (py - y);
            const float el = fminf(px, x), er = fmaxf(pw, w);
            const float et = fminf(py, y), eb = fmaxf(ph, h);
            const float ed = (er - el) * (er - el) + (eb - et) * (eb - et);
            const float da = atanf(w / (h + EPSF)) - atanf(pw / (ph + EPSF));
            const float v  = INV_PI2_4 * da * da;
            const float alpha = v / (1.0f - iou + v + EPSF);
            ciou = iou - cd / (ed + EPSF) - alpha * v;
        }
        float m = ciou;
        m = fmaxf(m, __shfl_xor_sync(0xFFFFFFFFu, m, 1));
        m = fmaxf(m, __shfl_xor_sync(0xFFFFFFFFu, m, 2));

        float contrib = 0.0f;
        if (lane < BPC && ciou >= m) {
            const float d = pC - ciou;
            contrib += 0.5f * d * d;           // object loss
            contrib -= 0.25f * pC * pC;        // removed from noobject term
            const float dx = (px - x) * (1.0f / CSF);
            const float dy = (py - y) * (1.0f / CSF);
            const float swp = sqrtf(fminf(fmaxf(pw, 0.0f), IMGF));
            const float shp = sqrtf(fminf(fmaxf(ph, 0.0f), IMGF));
            const float dw = swp - sqrtf(fabsf(w));
            const float dh = shp - sqrtf(fabsf(h));
            contrib += 5.0f * (0.5f * dx * dx + 0.5f * dy * dy
                               + (0.5f * dw * dw) * (1.0f / IMGF)
                               + (0.5f * dh * dh) * (1.0f / IMGF));
        }
        contrib += __shfl_xor_sync(0xFFFFFFFFu, contrib, 1);
        contrib += __shfl_xor_sync(0xFFFFFFFFu, contrib, 2);

        if (lane == 0)
            wacc += 0.5f * cls + contrib + 0.25f * S_conf2;
    }

    if (lane == 0) sred[wid] = wacc;
    __syncthreads();
    if (tid == 0) {
        float s = 0.0f;
        #pragma unroll
        for (int i = 0; i < 8; i++) s += sred[i];
        g_batch_loss[b] = s;
        __threadfence();
        int prev = atomicAdd(&g_count, 1);
        s_last = (prev == B - 1);
    }
    __syncthreads();

    // ---- Phase 3: last finished CTA -> deterministic final reduction ----
    if (s_last) {
        float a = 0.0f;
        for (int i = tid; i < B; i += 256) a += g_batch_loss[i];
        #pragma unroll
        for (int off = 16; off; off >>= 1)
            a += __shfl_xor_sync(0xFFFFFFFFu, a, off);
        if (lane == 0) sred[wid] = a;
        __syncthreads();
        if (tid == 0) {
            float s = 0.0f;
            #pragma unroll
            for (int i = 0; i < 8; i++) s += sred[i];
            out[0] = s / (float)B;
            g_count = 0;           // reset for next graph replay
        }
    }
}

extern "C" void kernel_launch(void* const* d_in, const int* in_sizes, int n_in,
                              void* d_out, int out_size)
{
    const float* predicts = (const float*)d_in[0];
    const float* labels   = (const float*)d_in[1];
    const int*   objnum   = (const int*)d_in[2];
    float* out = (float*)d_out;

    const int B = in_sizes[2];
    const int M = in_sizes[1] / (B * 5);

    yolo_fused_kernel<<<B, 256>>>(predicts, labels, objnum, out, B, M);
}

// round 4
// speedup vs baseline: 1.3349x; 1.0948x over previous
#include <cuda_runtime.h>
#include <cuda_bf16.h>
#include <math.h>

#define CELLN 14
#define NCLS  80
#define BPC   3
#define FEAT  95            // 80 + 3 + 12
#define CELLS2 196          // 14*14
#define PRED_PER_B 18620    // 196*95
#define CSF   32.0f
#define IMGF  448.0f
#define EPSF  1e-9f
#define INV_PI2_4 0.40528473456935109f   // 4/pi^2
#define MAXB  4096

__device__ float g_batch_loss[MAXB];
__device__ int   g_count = 0;

// ---------------------------------------------------------------------------
// One CTA (8 warps, 256 thr) per batch element.
//  Phase 1 : warp-per-cell coalesced stream; NO long reduce chain — one
//            butterfly shfl then 16 per-lane partials to smem. Loads of
//            successive cells are independent -> high MLP.
//  Phase 1b: 196 threads finish per-cell class sumsq (16 LDS each, odd
//            stride 17 -> conflict-free).
//  Phase 2 : per-object losses (mask cells, CIoU over 3 boxes).
//  Phase 3 : last-finished CTA does the deterministic batch reduction.
// ---------------------------------------------------------------------------
__global__ __launch_bounds__(256, 6)
void yolo_fused_kernel(const float* __restrict__ predicts,
                       const float* __restrict__ labels,
                       const int*   __restrict__ objects_num,
                       float* __restrict__ out, int B, int M)
{
    __shared__ float spart[CELLS2 * 17];   // per cell: 16 class-sumsq partials
    __shared__ float scell[CELLS2 * 16];   // per cell: features 80..94
    __shared__ float ssum2[CELLS2];        // per cell: class sum of squares
    __shared__ float sred[8];
    __shared__ float sS;
    __shared__ int   s_last;

    const int b    = blockIdx.x;
    const int tid  = threadIdx.x;
    const int lane = tid & 31;
    const int wid  = tid >> 5;

    const float* pb = predicts + (size_t)b * PRED_PER_B;

    // ---- Phase 1: stream; independent iterations -> load batching ----
    float conf2 = 0.0f;
    for (int cell = wid; cell < CELLS2; cell += 8) {
        const float* p = pb + cell * FEAT;
        const float a  = p[lane];
        const float bv = p[lane + 32];
        const float c  = (lane < 31) ? p[lane + 64] : 0.0f;

        float part = a * a + bv * bv;        // features [0,64)
        const float c2 = c * c;
        if (lane < 16) part += c2;           // features 64..79 (class)
        else if (lane < 19) conf2 += c2;     // features 80..82 (confidence)
        if (lane >= 16 && lane < 31)
            scell[cell * 16 + (lane - 16)] = c;   // features 80..94

        part += __shfl_xor_sync(0xFFFFFFFFu, part, 16);
        if (lane < 16) spart[cell * 17 + lane] = part;
    }
    // block-reduce confidence sumsq
    #pragma unroll
    for (int off = 16; off; off >>= 1)
        conf2 += __shfl_xor_sync(0xFFFFFFFFu, conf2, off);
    if (lane == 0) sred[wid] = conf2;
    __syncthreads();

    // ---- Phase 1b: finish per-cell class sumsq ----
    if (tid < CELLS2) {
        const float* sp = spart + tid * 17;
        float s = 0.0f;
        #pragma unroll
        for (int i = 0; i < 16; i++) s += sp[i];
        ssum2[tid] = s;
    }
    if (tid == 0) {
        float s = 0.0f;
        #pragma unroll
        for (int i = 0; i < 8; i++) s += sred[i];
        sS = s;
    }
    __syncthreads();
    const float S_conf2 = sS;
    __syncthreads();            // sred reused below

    // ---- Phase 2: per-object work ----
    int nobj = objects_num[b];
    if (nobj > M) nobj = M;
    const float* lb = labels + (size_t)b * M * 5;

    float wacc = 0.0f;
    for (int o = wid; o < nobj; o += 8) {
        const float x = lb[o * 5 + 0], y = lb[o * 5 + 1];
        const float w = lb[o * 5 + 2], h = lb[o * 5 + 3];
        const int   k = (int)lb[o * 5 + 4];

        const int ix0 = (int)floorf((x - 0.5f * w) * (1.0f / CSF));
        const int ix1 = (int)fminf(ceilf((x + 0.5f * w) * (1.0f / CSF)), (float)CELLN);
        const int iy0 = (int)floorf((y - 0.5f * h) * (1.0f / CSF));
        const int iy1 = (int)fminf(ceilf((y + 0.5f * h) * (1.0f / CSF)), (float)CELLN);
        const int nx  = max(0, ix1 - ix0);
        const int ny  = max(0, iy1 - iy0);
        const int cnt = nx * ny;

        // class loss over masked cells: ssum2[cell] - 2 p_k + 1
        float cls = 0.0f;
        for (int t = lane; t < cnt; t += 32) {
            const int iy = iy0 + t / nx;
            const int ix = ix0 + t % nx;
            const int cell = iy * CELLN + ix;
            cls += ssum2[cell] - 2.0f * __ldg(pb + cell * FEAT + k) + 1.0f;
        }
        #pragma unroll
        for (int off = 16; off; off >>= 1)
            cls += __shfl_xor_sync(0xFFFFFFFFu, cls, off);

        // center cell (conf + boxes live in smem)
        const int cx = (int)floorf(x * (1.0f / CSF));
        const int cy = (int)floorf(y * (1.0f / CSF));
        const float* sc = scell + (cy * CELLN + cx) * 16;

        float ciou = -1e30f;
        float pC = 0.f, px = 0.f, py = 0.f, pw = 0.f, ph = 0.f;
        if (lane < BPC) {
            pC = sc[lane];                          // features 80..82
            const float* bx = sc + BPC + 4 * lane;  // features 83..94
            px = bx[0] * CSF + (float)cx * CSF;
            py = bx[1] * CSF + (float)cy * CSF;
            pw = bx[2] * IMGF;
            ph = bx[3] * IMGF;

            // CIoU exactly per reference (incl. centers-vs-widths enclose quirk)
            const float x11 = px - 0.5f * pw, x12 = px + 0.5f * pw;
            const float y11 = py - 0.5f * ph, y12 = py + 0.5f * ph;
            const float x21 = x - 0.5f * w,   x22 = x + 0.5f * w;
            const float y21 = y - 0.5f * h,   y22 = y + 0.5f * h;
            const float iw = fmaxf(fminf(x12, x22) - fmaxf(x11, x21), 0.0f);
            const float ih = fmaxf(fminf(y12, y22) - fmaxf(y11, y21), 0.0f);
            const float inter = iw * ih;
            const float uni = pw * ph + w * h - inter;
            const float iou = inter / (uni + EPSF);
            const float cd  = (px - x) * (px - x) + (py - y) * (py - y);
            const float el = fminf(px, x), er = fmaxf(pw, w);
            const float et = fminf(py, y), eb = fmaxf(ph, h);
            const float ed = (er - el) * (er - el) + (eb - et) * (eb - et);
            const float da = atanf(w / (h + EPSF)) - atanf(pw / (ph + EPSF));
            const float v  = INV_PI2_4 * da * da;
            const float alpha = v / (1.0f - iou + v + EPSF);
            ciou = iou - cd / (ed + EPSF) - alpha * v;
        }
        float m = ciou;
        m = fmaxf(m, __shfl_xor_sync(0xFFFFFFFFu, m, 1));
        m = fmaxf(m, __shfl_xor_sync(0xFFFFFFFFu, m, 2));

        float contrib = 0.0f;
        if (lane < BPC && ciou >= m) {
            const float d = pC - ciou;
            contrib += 0.5f * d * d;           // object loss
            contrib -= 0.25f * pC * pC;        // removed from noobject term
            const float dx = (px - x) * (1.0f / CSF);
            const float dy = (py - y) * (1.0f / CSF);
            const float swp = sqrtf(fminf(fmaxf(pw, 0.0f), IMGF));
            const float shp = sqrtf(fminf(fmaxf(ph, 0.0f), IMGF));
            const float dw = swp - sqrtf(fabsf(w));
            const float dh = shp - sqrtf(fabsf(h));
            contrib += 5.0f * (0.5f * dx * dx + 0.5f * dy * dy
                               + (0.5f * dw * dw) * (1.0f / IMGF)
                               + (0.5f * dh * dh) * (1.0f / IMGF));
        }
        contrib += __shfl_xor_sync(0xFFFFFFFFu, contrib, 1);
        contrib += __shfl_xor_sync(0xFFFFFFFFu, contrib, 2);

        if (lane == 0)
            wacc += 0.5f * cls + contrib + 0.25f * S_conf2;
    }

    if (lane == 0) sred[wid] = wacc;
    __syncthreads();
    if (tid == 0) {
        float s = 0.0f;
        #pragma unroll
        for (int i = 0; i < 8; i++) s += sred[i];
        g_batch_loss[b] = s;
        __threadfence();
        int prev = atomicAdd(&g_count, 1);
        s_last = (prev == B - 1);
    }
    __syncthreads();

    // ---- Phase 3: last finished CTA -> deterministic final reduction ----
    if (s_last) {
        float a = 0.0f;
        for (int i = tid; i < B; i += 256) a += g_batch_loss[i];
        #pragma unroll
        for (int off = 16; off; off >>= 1)
            a += __shfl_xor_sync(0xFFFFFFFFu, a, off);
        if (lane == 0) sred[wid] = a;
        __syncthreads();
        if (tid == 0) {
            float s = 0.0f;
            #pragma unroll
            for (int i = 0; i < 8; i++) s += sred[i];
            out[0] = s / (float)B;
            g_count = 0;           // reset for next graph replay
        }
    }
}

extern "C" void kernel_launch(void* const* d_in, const int* in_sizes, int n_in,
                              void* d_out, int out_size)
{
    const float* predicts = (const float*)d_in[0];
    const float* labels   = (const float*)d_in[1];
    const int*   objnum   = (const int*)d_in[2];
    float* out = (float*)d_out;

    const int B = in_sizes[2];
    const int M = in_sizes[1] / (B * 5);

    yolo_fused_kernel<<<B, 256>>>(predicts, labels, objnum, out, B, M);
}